// round 11
// baseline (speedup 1.0000x reference)
#include <cuda_runtime.h>
#include <math.h>

#define NMAX 100000
#define DIN  256
#define HH1  256
#define HH2  128

// Scratch (allocation-free rule: __device__ globals)
__device__ float g_hs1 [(size_t)NMAX * HH1];
__device__ float g_agg1[(size_t)NMAX * HH1];
__device__ float g_hs2 [(size_t)NMAX * HH2];
__device__ float g_agg2[(size_t)NMAX * HH2];
__device__ int   g_deg [NMAX];
__device__ float g_dinv[NMAX];

// ---------------------------------------------------------------------------
// Degree / norm
// ---------------------------------------------------------------------------
__global__ void deg_init_kernel(int n) {
    int i = blockIdx.x * blockDim.x + threadIdx.x;
    if (i < n) g_deg[i] = 1;  // self loop
}

__global__ void deg_edge_kernel(const int* __restrict__ dst, int E) {
    for (int e = blockIdx.x * blockDim.x + threadIdx.x; e < E;
         e += gridDim.x * blockDim.x)
        atomicAdd(&g_deg[dst[e]], 1);
}

__global__ void dinv_kernel(int n) {
    int i = blockIdx.x * blockDim.x + threadIdx.x;
    if (i < n) g_dinv[i] = rsqrtf((float)g_deg[i]);
}

// ---------------------------------------------------------------------------
// Fused GEMM (double-buffered, packed fma.rn.f32x2, 8x8 register tile):
//   LAYER==1: hs1 = (X @ W1) * dinv[row];           agg1 = hs1  (self-loop init)
//   LAYER==2: A   = relu(dinv[row]*agg1 + b1[k])    (prologue fusion)
//             hs2 = (A @ W2) * dinv[row];           agg2 = hs2
// BM=128, BN=128, BK=16, 256 threads, 8x8 outputs/thread (4 row-pairs x 8 cols).
// ---------------------------------------------------------------------------
template<int LAYER>
__global__ __launch_bounds__(256) void gemm_kernel(
    const float* __restrict__ Ax, const float* __restrict__ B,
    const float* __restrict__ prebias, int M)
{
    constexpr int KD = (LAYER == 1) ? DIN : HH1;
    constexpr int ND = (LAYER == 1) ? HH1 : HH2;
    constexpr bool PRE = (LAYER == 2);
    const float* A  = (LAYER == 1) ? Ax : g_agg1;
    float* hs  = (LAYER == 1) ? g_hs1  : g_hs2;
    float* agg = (LAYER == 1) ? g_agg1 : g_agg2;

    constexpr int BM = 128, BN = 128, BK = 16;
    constexpr int NT = KD / BK;          // 16 tiles
    __shared__ float As[2][BK][BM];      // transposed: As[k][m]
    __shared__ float Bs[2][BK][BN];

    int tid = threadIdx.x;
    int blockM = blockIdx.y * BM;
    int blockN = blockIdx.x * BN;

    int ty = tid >> 4;          // 0..15 -> 8 rows each
    int tx = tid & 15;          // 0..15 -> 8 cols each

    // Packed accumulators: accp[ii][j] = rows (ty*8+2ii, +1) x col (tx*8+j)
    unsigned long long accp[4][8];
#pragma unroll
    for (int ii = 0; ii < 4; ii++)
#pragma unroll
        for (int j = 0; j < 8; j++) accp[ii][j] = 0ull;

    // A fill: row = tid&127, col half = (tid>>7)*8  -> conflict-free STS
    int arow = tid & 127;
    int acol = (tid >> 7) * 8;
    // B fill: row = tid>>4, col = (tid&15)*8
    int brow = tid >> 4;
    int bcol = (tid & 15) * 8;

    int grow = blockM + arow;
    bool okA = grow < M;
    float dvA = 0.f;
    if (PRE && okA) dvA = g_dinv[grow];

    float4 ra0, ra1, rb0, rb1;

    // ---- register-stage loader for tile kt ----
    auto load_regs = [&](int kt) {
        ra0 = make_float4(0.f, 0.f, 0.f, 0.f);
        ra1 = make_float4(0.f, 0.f, 0.f, 0.f);
        if (okA) {
            const float* ap = A + (size_t)grow * KD + kt + acol;
            ra0 = *(const float4*)(ap);
            ra1 = *(const float4*)(ap + 4);
            if (PRE) {
                float4 b0 = *(const float4*)(prebias + kt + acol);
                float4 b1v = *(const float4*)(prebias + kt + acol + 4);
                ra0.x = fmaxf(fmaf(dvA, ra0.x, b0.x), 0.f);
                ra0.y = fmaxf(fmaf(dvA, ra0.y, b0.y), 0.f);
                ra0.z = fmaxf(fmaf(dvA, ra0.z, b0.z), 0.f);
                ra0.w = fmaxf(fmaf(dvA, ra0.w, b0.w), 0.f);
                ra1.x = fmaxf(fmaf(dvA, ra1.x, b1v.x), 0.f);
                ra1.y = fmaxf(fmaf(dvA, ra1.y, b1v.y), 0.f);
                ra1.z = fmaxf(fmaf(dvA, ra1.z, b1v.z), 0.f);
                ra1.w = fmaxf(fmaf(dvA, ra1.w, b1v.w), 0.f);
            }
        }
        const float* bp = B + (size_t)(kt + brow) * ND + blockN + bcol;
        rb0 = *(const float4*)(bp);
        rb1 = *(const float4*)(bp + 4);
    };

    auto store_smem = [&](int buf) {
        As[buf][acol + 0][arow] = ra0.x;
        As[buf][acol + 1][arow] = ra0.y;
        As[buf][acol + 2][arow] = ra0.z;
        As[buf][acol + 3][arow] = ra0.w;
        As[buf][acol + 4][arow] = ra1.x;
        As[buf][acol + 5][arow] = ra1.y;
        As[buf][acol + 6][arow] = ra1.z;
        As[buf][acol + 7][arow] = ra1.w;
        *(float4*)&Bs[buf][brow][bcol]     = rb0;
        *(float4*)&Bs[buf][brow][bcol + 4] = rb1;
    };

    // prologue: fill buffer 0
    load_regs(0);
    store_smem(0);
    __syncthreads();

#pragma unroll 1
    for (int t = 0; t < NT; t++) {
        int cur = t & 1;
        bool more = (t + 1 < NT);
        if (more) load_regs((t + 1) * BK);   // overlap with compute below

#pragma unroll
        for (int k = 0; k < BK; k++) {
            // A fragment: 8 contiguous rows -> 4 packed f32x2 pairs (broadcast
            // within warp: only 2 distinct addresses).
            unsigned long long ap[4];
            *(float4*)&ap[0] = *(const float4*)&As[cur][k][ty * 8];
            *(float4*)&ap[2] = *(const float4*)&As[cur][k][ty * 8 + 4];
            float b[8];
            *(float4*)&b[0] = *(const float4*)&Bs[cur][k][tx * 8];
            *(float4*)&b[4] = *(const float4*)&Bs[cur][k][tx * 8 + 4];
            // Two groups of 4 cols to cap live bp registers.
#pragma unroll
            for (int jh = 0; jh < 2; jh++) {
                unsigned long long bp[4];
#pragma unroll
                for (int j = 0; j < 4; j++)
                    asm("mov.b64 %0, {%1, %2};"
                        : "=l"(bp[j]) : "f"(b[jh * 4 + j]), "f"(b[jh * 4 + j]));
#pragma unroll
                for (int ii = 0; ii < 4; ii++)
#pragma unroll
                    for (int j = 0; j < 4; j++)
                        asm("fma.rn.f32x2 %0, %1, %2, %3;"
                            : "=l"(accp[ii][jh * 4 + j])
                            : "l"(ap[ii]), "l"(bp[j]), "l"(accp[ii][jh * 4 + j]));
            }
        }

        if (more) store_smem(cur ^ 1);
        __syncthreads();
    }

    // Epilogue: unpack, scale by dinv[row]; write hs (streaming) + agg (self-loop)
#pragma unroll
    for (int ii = 0; ii < 4; ii++) {
        float lo[8], hi[8];
#pragma unroll
        for (int j = 0; j < 8; j++)
            asm("mov.b64 {%0, %1}, %2;" : "=f"(lo[j]), "=f"(hi[j]) : "l"(accp[ii][j]));
#pragma unroll
        for (int h = 0; h < 2; h++) {
            int r = blockM + ty * 8 + ii * 2 + h;
            if (r < M) {
                float dv = g_dinv[r];
                const float* s = h ? hi : lo;
                float4 o0, o1;
                o0.x = s[0] * dv; o0.y = s[1] * dv; o0.z = s[2] * dv; o0.w = s[3] * dv;
                o1.x = s[4] * dv; o1.y = s[5] * dv; o1.z = s[6] * dv; o1.w = s[7] * dv;
                size_t off = (size_t)r * ND + blockN + tx * 8;
                __stcs((float4*)(hs + off),     o0);   // read-once stream
                __stcs((float4*)(hs + off + 4), o1);
                *(float4*)(agg + off)     = o0;
                *(float4*)(agg + off + 4) = o1;
            }
        }
    }
}

// ---------------------------------------------------------------------------
// Edge scatter: EPW edges per warp, agg[dst] += hs[src].
// All src/dst index loads, then ALL gathers (MLP = EPW*NIT in flight),
// then all v4 REDs. Raises per-warp memory-level parallelism 4x.
// ---------------------------------------------------------------------------
template<int LAYER>
__global__ __launch_bounds__(256) void scatter_kernel(
    const int* __restrict__ src, const int* __restrict__ dst, int E)
{
    constexpr int F = (LAYER == 1) ? HH1 : HH2;
    constexpr int NIT = F / 128;   // float4s per lane per edge
    constexpr int EPW = 4;         // edges per warp
    const float* hs = (LAYER == 1) ? g_hs1  : g_hs2;
    float* agg      = (LAYER == 1) ? g_agg1 : g_agg2;

    int g = blockIdx.x * blockDim.x + threadIdx.x;
    int warp = g >> 5;
    int lane = g & 31;
    int e0 = warp * EPW;
    if (e0 >= E) return;

    int s[EPW], d[EPW];
#pragma unroll
    for (int w = 0; w < EPW; w++) {
        int e = e0 + w;
        if (e < E) {
            s[w] = __ldg(src + e);    // warp-uniform broadcast load
            d[w] = __ldg(dst + e);
        }
    }

    float4 v[EPW][NIT];
#pragma unroll
    for (int w = 0; w < EPW; w++) {
        if (e0 + w < E) {
            const float4* sp = (const float4*)(hs + (size_t)s[w] * F);
#pragma unroll
            for (int i = 0; i < NIT; i++)
                v[w][i] = __ldg(sp + lane + i * 32);
        }
    }

#pragma unroll
    for (int w = 0; w < EPW; w++) {
        if (e0 + w < E) {
            float4* dp = (float4*)(agg + (size_t)d[w] * F);
#pragma unroll
            for (int i = 0; i < NIT; i++)
                asm volatile("red.global.add.v4.f32 [%0], {%1, %2, %3, %4};"
                             :: "l"(dp + lane + i * 32),
                                "f"(v[w][i].x), "f"(v[w][i].y),
                                "f"(v[w][i].z), "f"(v[w][i].w)
                             : "memory");
        }
    }
}

// ---------------------------------------------------------------------------
// Final: out = dinv[row]*agg2 + b2
// ---------------------------------------------------------------------------
__global__ void finalize_kernel(const float* __restrict__ b2,
                                float* __restrict__ out, int n)
{
    int idx = blockIdx.x * blockDim.x + threadIdx.x;   // over n * HH2/4
    int total = n * (HH2 / 4);
    if (idx >= total) return;
    int i  = idx / (HH2 / 4);
    int j4 = idx % (HH2 / 4);
    float dv = g_dinv[i];
    float4 v  = *(const float4*)(g_agg2 + (size_t)i * HH2 + j4 * 4);
    float4 bb = *(const float4*)(b2 + j4 * 4);
    float4 o;
    o.x = fmaf(dv, v.x, bb.x);
    o.y = fmaf(dv, v.y, bb.y);
    o.z = fmaf(dv, v.z, bb.z);
    o.w = fmaf(dv, v.w, bb.w);
    *(float4*)(out + (size_t)i * HH2 + j4 * 4) = o;
}

// ---------------------------------------------------------------------------
extern "C" void kernel_launch(void* const* d_in, const int* in_sizes, int n_in,
                              void* d_out, int out_size)
{
    const float* x  = (const float*)d_in[0];
    const float* W1 = (const float*)d_in[1];
    const float* b1 = (const float*)d_in[2];
    const float* W2 = (const float*)d_in[3];
    const float* b2 = (const float*)d_in[4];
    const int* edge = (const int*)d_in[5];

    int n = in_sizes[0] / DIN;
    int E = in_sizes[5] / 2;
    const int* src = edge;
    const int* dst = edge + E;
    float* out = (float*)d_out;

    int tb = 256;

    deg_init_kernel<<<(n + tb - 1) / tb, tb>>>(n);
    deg_edge_kernel<<<592, 512>>>(dst, E);   // ~4 blocks/SM grid-stride
    dinv_kernel<<<(n + tb - 1) / tb, tb>>>(n);

    dim3 g1(HH1 / 128, (n + 127) / 128);
    gemm_kernel<1><<<g1, 256>>>(x, W1, nullptr, n);

    // EPW=4 edges/warp: threads = ceil(E/4) warps * 32
    long long warps = ((long long)E + 3) / 4;
    long long t1 = warps * 32;
    scatter_kernel<1><<<(unsigned)((t1 + tb - 1) / tb), tb>>>(src, dst, E);

    dim3 g2(HH2 / 128, (n + 127) / 128);
    gemm_kernel<2><<<g2, 256>>>(nullptr, W2, b1, n);

    scatter_kernel<2><<<(unsigned)((t1 + tb - 1) / tb), tb>>>(src, dst, E);

    finalize_kernel<<<(n * (HH2 / 4) + tb - 1) / tb, tb>>>(b2, out, n);
}

// round 12
// speedup vs baseline: 1.0306x; 1.0306x over previous
#include <cuda_runtime.h>
#include <math.h>

#define NMAX 100000
#define DIN  256
#define HH1  256
#define HH2  128

// Scratch (allocation-free rule: __device__ globals)
__device__ float g_hs1 [(size_t)NMAX * HH1];
__device__ float g_agg1[(size_t)NMAX * HH1];
__device__ float g_hs2 [(size_t)NMAX * HH2];
__device__ float g_agg2[(size_t)NMAX * HH2];
__device__ int   g_deg [NMAX];
__device__ float g_dinv[NMAX];

// ---------------------------------------------------------------------------
// Degree / norm
// ---------------------------------------------------------------------------
__global__ void deg_init_kernel(int n) {
    int i = blockIdx.x * blockDim.x + threadIdx.x;
    if (i < n) g_deg[i] = 1;  // self loop
}

__global__ void deg_edge_kernel(const int* __restrict__ dst, int E) {
    for (int e = blockIdx.x * blockDim.x + threadIdx.x; e < E;
         e += gridDim.x * blockDim.x)
        atomicAdd(&g_deg[dst[e]], 1);
}

__global__ void dinv_kernel(int n) {
    int i = blockIdx.x * blockDim.x + threadIdx.x;
    if (i < n) g_dinv[i] = rsqrtf((float)g_deg[i]);
}

// ---------------------------------------------------------------------------
// Fused GEMM (double-buffered, packed fma.rn.f32x2, 8x8 register tile,
// B tile in TWO 64-col halves so all B STS/LDS are stride-16B conflict-free):
//   LAYER==1: hs1 = (X @ W1) * dinv[row];           agg1 = hs1  (self-loop init)
//   LAYER==2: A   = relu(dinv[row]*agg1 + b1[k])    (prologue fusion)
//             hs2 = (A @ W2) * dinv[row];           agg2 = hs2
// BM=128, BN=128, BK=16, 256 threads, 8x8 outputs/thread (4 row-pairs x 8 cols:
// 4 cols in half0 [blockN+tx*4], 4 cols in half1 [blockN+64+tx*4]).
// ---------------------------------------------------------------------------
template<int LAYER>
__global__ __launch_bounds__(256) void gemm_kernel(
    const float* __restrict__ Ax, const float* __restrict__ B,
    const float* __restrict__ prebias, int M)
{
    constexpr int KD = (LAYER == 1) ? DIN : HH1;
    constexpr int ND = (LAYER == 1) ? HH1 : HH2;
    constexpr bool PRE = (LAYER == 2);
    const float* A  = (LAYER == 1) ? Ax : g_agg1;
    float* hs  = (LAYER == 1) ? g_hs1  : g_hs2;
    float* agg = (LAYER == 1) ? g_agg1 : g_agg2;

    constexpr int BM = 128, BN = 128, BK = 16;
    constexpr int NT = KD / BK;          // 16 tiles
    __shared__ float As[2][BK][BM];      // transposed: As[k][m]
    __shared__ float Bs[2][BK][2][64];   // two 64-col halves per k-row

    int tid = threadIdx.x;
    int blockM = blockIdx.y * BM;
    int blockN = blockIdx.x * BN;

    int ty = tid >> 4;          // 0..15 -> 8 rows each
    int tx = tid & 15;          // 0..15 -> 4+4 cols each

    // Packed accumulators: accp[ii][j]: rows (ty*8+2ii, +1);
    // j<4 -> col blockN+tx*4+j (half0), j>=4 -> col blockN+64+tx*4+(j-4) (half1)
    unsigned long long accp[4][8];
#pragma unroll
    for (int ii = 0; ii < 4; ii++)
#pragma unroll
        for (int j = 0; j < 8; j++) accp[ii][j] = 0ull;

    // A fill: row = tid&127, col half = (tid>>7)*8  -> conflict-free STS
    int arow = tid & 127;
    int acol = (tid >> 7) * 8;
    // B fill: row = tid>>4, 4 cols at q in EACH half
    int brow = tid >> 4;
    int bq   = (tid & 15) * 4;

    int grow = blockM + arow;
    bool okA = grow < M;
    float dvA = 0.f;
    if (PRE && okA) dvA = g_dinv[grow];

    float4 ra0, ra1, rb0, rb1;

    // ---- register-stage loader for tile kt ----
    auto load_regs = [&](int kt) {
        ra0 = make_float4(0.f, 0.f, 0.f, 0.f);
        ra1 = make_float4(0.f, 0.f, 0.f, 0.f);
        if (okA) {
            const float* ap = A + (size_t)grow * KD + kt + acol;
            ra0 = *(const float4*)(ap);
            ra1 = *(const float4*)(ap + 4);
            if (PRE) {
                float4 b0 = *(const float4*)(prebias + kt + acol);
                float4 b1v = *(const float4*)(prebias + kt + acol + 4);
                ra0.x = fmaxf(fmaf(dvA, ra0.x, b0.x), 0.f);
                ra0.y = fmaxf(fmaf(dvA, ra0.y, b0.y), 0.f);
                ra0.z = fmaxf(fmaf(dvA, ra0.z, b0.z), 0.f);
                ra0.w = fmaxf(fmaf(dvA, ra0.w, b0.w), 0.f);
                ra1.x = fmaxf(fmaf(dvA, ra1.x, b1v.x), 0.f);
                ra1.y = fmaxf(fmaf(dvA, ra1.y, b1v.y), 0.f);
                ra1.z = fmaxf(fmaf(dvA, ra1.z, b1v.z), 0.f);
                ra1.w = fmaxf(fmaf(dvA, ra1.w, b1v.w), 0.f);
            }
        }
        const float* bp = B + (size_t)(kt + brow) * ND + blockN + bq;
        rb0 = *(const float4*)(bp);        // cols bq..bq+3   (half0)
        rb1 = *(const float4*)(bp + 64);   // cols 64+bq..+3  (half1)
    };

    auto store_smem = [&](int buf) {
        As[buf][acol + 0][arow] = ra0.x;
        As[buf][acol + 1][arow] = ra0.y;
        As[buf][acol + 2][arow] = ra0.z;
        As[buf][acol + 3][arow] = ra0.w;
        As[buf][acol + 4][arow] = ra1.x;
        As[buf][acol + 5][arow] = ra1.y;
        As[buf][acol + 6][arow] = ra1.z;
        As[buf][acol + 7][arow] = ra1.w;
        *(float4*)&Bs[buf][brow][0][bq] = rb0;   // stride-16B: conflict-free
        *(float4*)&Bs[buf][brow][1][bq] = rb1;
    };

    // prologue: fill buffer 0
    load_regs(0);
    store_smem(0);
    __syncthreads();

#pragma unroll 1
    for (int t = 0; t < NT; t++) {
        int cur = t & 1;
        bool more = (t + 1 < NT);
        if (more) load_regs((t + 1) * BK);   // overlap with compute below

#pragma unroll
        for (int k = 0; k < BK; k++) {
            // A fragment: 8 contiguous rows -> 4 packed f32x2 pairs (broadcast
            // within warp: only 2 distinct addresses).
            unsigned long long ap[4];
            *(float4*)&ap[0] = *(const float4*)&As[cur][k][ty * 8];
            *(float4*)&ap[2] = *(const float4*)&As[cur][k][ty * 8 + 4];
            // B fragment: tx*4 in each half -> 16B stride, conflict-free
            float b[8];
            *(float4*)&b[0] = *(const float4*)&Bs[cur][k][0][tx * 4];
            *(float4*)&b[4] = *(const float4*)&Bs[cur][k][1][tx * 4];
            // Two groups of 4 cols to cap live bp registers.
#pragma unroll
            for (int jh = 0; jh < 2; jh++) {
                unsigned long long bp[4];
#pragma unroll
                for (int j = 0; j < 4; j++)
                    asm("mov.b64 %0, {%1, %2};"
                        : "=l"(bp[j]) : "f"(b[jh * 4 + j]), "f"(b[jh * 4 + j]));
#pragma unroll
                for (int ii = 0; ii < 4; ii++)
#pragma unroll
                    for (int j = 0; j < 4; j++)
                        asm("fma.rn.f32x2 %0, %1, %2, %3;"
                            : "=l"(accp[ii][jh * 4 + j])
                            : "l"(ap[ii]), "l"(bp[j]), "l"(accp[ii][jh * 4 + j]));
            }
        }

        if (more) store_smem(cur ^ 1);
        __syncthreads();
    }

    // Epilogue: unpack, scale by dinv[row]; write hs (streaming) + agg (self-loop)
    // j<4 -> cols blockN+tx*4.., j>=4 -> cols blockN+64+tx*4..
#pragma unroll
    for (int ii = 0; ii < 4; ii++) {
        float lo[8], hi[8];
#pragma unroll
        for (int j = 0; j < 8; j++)
            asm("mov.b64 {%0, %1}, %2;" : "=f"(lo[j]), "=f"(hi[j]) : "l"(accp[ii][j]));
#pragma unroll
        for (int h = 0; h < 2; h++) {
            int r = blockM + ty * 8 + ii * 2 + h;
            if (r < M) {
                float dv = g_dinv[r];
                const float* s = h ? hi : lo;
                float4 o0, o1;
                o0.x = s[0] * dv; o0.y = s[1] * dv; o0.z = s[2] * dv; o0.w = s[3] * dv;
                o1.x = s[4] * dv; o1.y = s[5] * dv; o1.z = s[6] * dv; o1.w = s[7] * dv;
                size_t off0 = (size_t)r * ND + blockN + tx * 4;
                size_t off1 = off0 + 64;
                __stcs((float4*)(hs + off0), o0);   // read-once stream
                __stcs((float4*)(hs + off1), o1);
                *(float4*)(agg + off0) = o0;
                *(float4*)(agg + off1) = o1;
            }
        }
    }
}

// ---------------------------------------------------------------------------
// Edge scatter: EPW edges per warp, agg[dst] += hs[src].
// All src/dst index loads, then ALL gathers (MLP = EPW*NIT in flight),
// then all v4 REDs. (Correctness validated on silicon in R11.)
// ---------------------------------------------------------------------------
template<int LAYER>
__global__ __launch_bounds__(256) void scatter_kernel(
    const int* __restrict__ src, const int* __restrict__ dst, int E)
{
    constexpr int F = (LAYER == 1) ? HH1 : HH2;
    constexpr int NIT = F / 128;   // float4s per lane per edge
    constexpr int EPW = 4;         // edges per warp
    const float* hs = (LAYER == 1) ? g_hs1  : g_hs2;
    float* agg      = (LAYER == 1) ? g_agg1 : g_agg2;

    int g = blockIdx.x * blockDim.x + threadIdx.x;
    int warp = g >> 5;
    int lane = g & 31;
    int e0 = warp * EPW;
    if (e0 >= E) return;

    int s[EPW], d[EPW];
#pragma unroll
    for (int w = 0; w < EPW; w++) {
        int e = e0 + w;
        if (e < E) {
            s[w] = __ldg(src + e);    // warp-uniform broadcast load
            d[w] = __ldg(dst + e);
        }
    }

    float4 v[EPW][NIT];
#pragma unroll
    for (int w = 0; w < EPW; w++) {
        if (e0 + w < E) {
            const float4* sp = (const float4*)(hs + (size_t)s[w] * F);
#pragma unroll
            for (int i = 0; i < NIT; i++)
                v[w][i] = __ldg(sp + lane + i * 32);
        }
    }

#pragma unroll
    for (int w = 0; w < EPW; w++) {
        if (e0 + w < E) {
            float4* dp = (float4*)(agg + (size_t)d[w] * F);
#pragma unroll
            for (int i = 0; i < NIT; i++)
                asm volatile("red.global.add.v4.f32 [%0], {%1, %2, %3, %4};"
                             :: "l"(dp + lane + i * 32),
                                "f"(v[w][i].x), "f"(v[w][i].y),
                                "f"(v[w][i].z), "f"(v[w][i].w)
                             : "memory");
        }
    }
}

// ---------------------------------------------------------------------------
// Final: out = dinv[row]*agg2 + b2
// ---------------------------------------------------------------------------
__global__ void finalize_kernel(const float* __restrict__ b2,
                                float* __restrict__ out, int n)
{
    int idx = blockIdx.x * blockDim.x + threadIdx.x;   // over n * HH2/4
    int total = n * (HH2 / 4);
    if (idx >= total) return;
    int i  = idx / (HH2 / 4);
    int j4 = idx % (HH2 / 4);
    float dv = g_dinv[i];
    float4 v  = *(const float4*)(g_agg2 + (size_t)i * HH2 + j4 * 4);
    float4 bb = *(const float4*)(b2 + j4 * 4);
    float4 o;
    o.x = fmaf(dv, v.x, bb.x);
    o.y = fmaf(dv, v.y, bb.y);
    o.z = fmaf(dv, v.z, bb.z);
    o.w = fmaf(dv, v.w, bb.w);
    *(float4*)(out + (size_t)i * HH2 + j4 * 4) = o;
}

// ---------------------------------------------------------------------------
extern "C" void kernel_launch(void* const* d_in, const int* in_sizes, int n_in,
                              void* d_out, int out_size)
{
    const float* x  = (const float*)d_in[0];
    const float* W1 = (const float*)d_in[1];
    const float* b1 = (const float*)d_in[2];
    const float* W2 = (const float*)d_in[3];
    const float* b2 = (const float*)d_in[4];
    const int* edge = (const int*)d_in[5];

    int n = in_sizes[0] / DIN;
    int E = in_sizes[5] / 2;
    const int* src = edge;
    const int* dst = edge + E;
    float* out = (float*)d_out;

    int tb = 256;

    deg_init_kernel<<<(n + tb - 1) / tb, tb>>>(n);
    deg_edge_kernel<<<592, 512>>>(dst, E);   // ~4 blocks/SM grid-stride
    dinv_kernel<<<(n + tb - 1) / tb, tb>>>(n);

    dim3 g1(HH1 / 128, (n + 127) / 128);
    gemm_kernel<1><<<g1, 256>>>(x, W1, nullptr, n);

    // EPW=4 edges/warp: threads = ceil(E/4) warps * 32
    long long warps = ((long long)E + 3) / 4;
    long long t1 = warps * 32;
    scatter_kernel<1><<<(unsigned)((t1 + tb - 1) / tb), tb>>>(src, dst, E);

    dim3 g2(HH2 / 128, (n + 127) / 128);
    gemm_kernel<2><<<g2, 256>>>(nullptr, W2, b1, n);

    scatter_kernel<2><<<(unsigned)((t1 + tb - 1) / tb), tb>>>(src, dst, E);

    finalize_kernel<<<(n * (HH2 / 4) + tb - 1) / tb, tb>>>(b2, out, n);
}

// round 13
// speedup vs baseline: 1.1651x; 1.1305x over previous
#include <cuda_runtime.h>
#include <math.h>

#define NMAX 100000
#define DIN  256
#define HH1  256
#define HH2  128

// Scratch (allocation-free rule: __device__ globals)
__device__ float g_hs1 [(size_t)NMAX * HH1];
__device__ float g_agg1[(size_t)NMAX * HH1];
__device__ float g_hs2 [(size_t)NMAX * HH2];
__device__ float g_agg2[(size_t)NMAX * HH2];
__device__ int   g_deg [NMAX];
__device__ float g_dinv[NMAX];

// ---------------------------------------------------------------------------
// Degree / norm
// ---------------------------------------------------------------------------
__global__ void deg_init_kernel(int n) {
    int i = blockIdx.x * blockDim.x + threadIdx.x;
    if (i < n) g_deg[i] = 1;  // self loop
}

__global__ void deg_edge_kernel(const int* __restrict__ dst, int E) {
    for (int e = blockIdx.x * blockDim.x + threadIdx.x; e < E;
         e += gridDim.x * blockDim.x)
        atomicAdd(&g_deg[dst[e]], 1);
}

__global__ void dinv_kernel(int n) {
    int i = blockIdx.x * blockDim.x + threadIdx.x;
    if (i < n) g_dinv[i] = rsqrtf((float)g_deg[i]);
}

// ---------------------------------------------------------------------------
// Fused GEMM (double-buffered, packed fma.rn.f32x2, 8x8 register tile,
// B tile in TWO 64-col halves: all B STS/LDS stride-16B conflict-free;
// __launch_bounds__(256,2) pins regs <=128 so 2 CTAs/SM co-reside):
//   LAYER==1: hs1 = (X @ W1) * dinv[row];           agg1 = hs1  (self-loop init)
//   LAYER==2: A   = relu(dinv[row]*agg1 + b1[k])    (prologue fusion)
//             hs2 = (A @ W2) * dinv[row];           agg2 = hs2
// BM=128, BN=128, BK=16, 256 threads, 8x8 outputs/thread.
// ---------------------------------------------------------------------------
template<int LAYER>
__global__ __launch_bounds__(256, 2) void gemm_kernel(
    const float* __restrict__ Ax, const float* __restrict__ B,
    const float* __restrict__ prebias, int M)
{
    constexpr int KD = (LAYER == 1) ? DIN : HH1;
    constexpr int ND = (LAYER == 1) ? HH1 : HH2;
    constexpr bool PRE = (LAYER == 2);
    const float* A  = (LAYER == 1) ? Ax : g_agg1;
    float* hs  = (LAYER == 1) ? g_hs1  : g_hs2;
    float* agg = (LAYER == 1) ? g_agg1 : g_agg2;

    constexpr int BM = 128, BN = 128, BK = 16;
    constexpr int NT = KD / BK;          // 16 tiles
    __shared__ float As[2][BK][BM];      // transposed: As[k][m]
    __shared__ float Bs[2][BK][2][64];   // two 64-col halves per k-row

    int tid = threadIdx.x;
    int blockM = blockIdx.y * BM;
    int blockN = blockIdx.x * BN;

    int ty = tid >> 4;          // 0..15 -> 8 rows each
    int tx = tid & 15;          // 0..15 -> 4+4 cols each

    // Packed accumulators: accp[ii][j]: rows (ty*8+2ii, +1);
    // j<4 -> col blockN+tx*4+j (half0), j>=4 -> col blockN+64+tx*4+(j-4) (half1)
    unsigned long long accp[4][8];
#pragma unroll
    for (int ii = 0; ii < 4; ii++)
#pragma unroll
        for (int j = 0; j < 8; j++) accp[ii][j] = 0ull;

    // A fill: row = tid&127, col half = (tid>>7)*8  -> conflict-free STS
    int arow = tid & 127;
    int acol = (tid >> 7) * 8;
    // B fill: row = tid>>4, 4 cols at q in EACH half
    int brow = tid >> 4;
    int bq   = (tid & 15) * 4;

    int grow = blockM + arow;
    bool okA = grow < M;
    float dvA = 0.f;
    if (PRE && okA) dvA = g_dinv[grow];

    float4 ra0, ra1, rb0, rb1;

    // ---- register-stage loader for tile kt ----
    auto load_regs = [&](int kt) {
        ra0 = make_float4(0.f, 0.f, 0.f, 0.f);
        ra1 = make_float4(0.f, 0.f, 0.f, 0.f);
        if (okA) {
            const float* ap = A + (size_t)grow * KD + kt + acol;
            ra0 = *(const float4*)(ap);
            ra1 = *(const float4*)(ap + 4);
            if (PRE) {
                float4 b0 = *(const float4*)(prebias + kt + acol);
                float4 b1v = *(const float4*)(prebias + kt + acol + 4);
                ra0.x = fmaxf(fmaf(dvA, ra0.x, b0.x), 0.f);
                ra0.y = fmaxf(fmaf(dvA, ra0.y, b0.y), 0.f);
                ra0.z = fmaxf(fmaf(dvA, ra0.z, b0.z), 0.f);
                ra0.w = fmaxf(fmaf(dvA, ra0.w, b0.w), 0.f);
                ra1.x = fmaxf(fmaf(dvA, ra1.x, b1v.x), 0.f);
                ra1.y = fmaxf(fmaf(dvA, ra1.y, b1v.y), 0.f);
                ra1.z = fmaxf(fmaf(dvA, ra1.z, b1v.z), 0.f);
                ra1.w = fmaxf(fmaf(dvA, ra1.w, b1v.w), 0.f);
            }
        }
        const float* bp = B + (size_t)(kt + brow) * ND + blockN + bq;
        rb0 = *(const float4*)(bp);        // cols bq..bq+3   (half0)
        rb1 = *(const float4*)(bp + 64);   // cols 64+bq..+3  (half1)
    };

    auto store_smem = [&](int buf) {
        As[buf][acol + 0][arow] = ra0.x;
        As[buf][acol + 1][arow] = ra0.y;
        As[buf][acol + 2][arow] = ra0.z;
        As[buf][acol + 3][arow] = ra0.w;
        As[buf][acol + 4][arow] = ra1.x;
        As[buf][acol + 5][arow] = ra1.y;
        As[buf][acol + 6][arow] = ra1.z;
        As[buf][acol + 7][arow] = ra1.w;
        *(float4*)&Bs[buf][brow][0][bq] = rb0;   // stride-16B: conflict-free
        *(float4*)&Bs[buf][brow][1][bq] = rb1;
    };

    // prologue: fill buffer 0
    load_regs(0);
    store_smem(0);
    __syncthreads();

#pragma unroll 1
    for (int t = 0; t < NT; t++) {
        int cur = t & 1;
        bool more = (t + 1 < NT);
        if (more) load_regs((t + 1) * BK);   // overlap with compute below

#pragma unroll
        for (int k = 0; k < BK; k++) {
            // A fragment: 8 contiguous rows -> 4 packed f32x2 pairs (broadcast
            // within warp: only 2 distinct addresses).
            unsigned long long ap[4];
            *(float4*)&ap[0] = *(const float4*)&As[cur][k][ty * 8];
            *(float4*)&ap[2] = *(const float4*)&As[cur][k][ty * 8 + 4];
            // B fragment: tx*4 in each half -> 16B stride, conflict-free
            float b[8];
            *(float4*)&b[0] = *(const float4*)&Bs[cur][k][0][tx * 4];
            *(float4*)&b[4] = *(const float4*)&Bs[cur][k][1][tx * 4];
            // Two groups of 4 cols to cap live bp registers.
#pragma unroll
            for (int jh = 0; jh < 2; jh++) {
                unsigned long long bp[4];
#pragma unroll
                for (int j = 0; j < 4; j++)
                    asm("mov.b64 %0, {%1, %2};"
                        : "=l"(bp[j]) : "f"(b[jh * 4 + j]), "f"(b[jh * 4 + j]));
#pragma unroll
                for (int ii = 0; ii < 4; ii++)
#pragma unroll
                    for (int j = 0; j < 4; j++)
                        asm("fma.rn.f32x2 %0, %1, %2, %3;"
                            : "=l"(accp[ii][jh * 4 + j])
                            : "l"(ap[ii]), "l"(bp[j]), "l"(accp[ii][jh * 4 + j]));
            }
        }

        if (more) store_smem(cur ^ 1);
        __syncthreads();
    }

    // Epilogue: unpack, scale by dinv[row]; write hs (streaming) + agg (self-loop)
    // j<4 -> cols blockN+tx*4.., j>=4 -> cols blockN+64+tx*4..
#pragma unroll
    for (int ii = 0; ii < 4; ii++) {
        float lo[8], hi[8];
#pragma unroll
        for (int j = 0; j < 8; j++)
            asm("mov.b64 {%0, %1}, %2;" : "=f"(lo[j]), "=f"(hi[j]) : "l"(accp[ii][j]));
#pragma unroll
        for (int h = 0; h < 2; h++) {
            int r = blockM + ty * 8 + ii * 2 + h;
            if (r < M) {
                float dv = g_dinv[r];
                const float* s = h ? hi : lo;
                float4 o0, o1;
                o0.x = s[0] * dv; o0.y = s[1] * dv; o0.z = s[2] * dv; o0.w = s[3] * dv;
                o1.x = s[4] * dv; o1.y = s[5] * dv; o1.z = s[6] * dv; o1.w = s[7] * dv;
                size_t off0 = (size_t)r * ND + blockN + tx * 4;
                size_t off1 = off0 + 64;
                __stcs((float4*)(hs + off0), o0);   // read-once stream
                __stcs((float4*)(hs + off1), o1);
                *(float4*)(agg + off0) = o0;
                *(float4*)(agg + off1) = o1;
            }
        }
    }
}

// ---------------------------------------------------------------------------
// Edge scatter: EPW edges per warp, agg[dst] += hs[src].
// All src/dst index loads, then ALL gathers (MLP = EPW*NIT in flight),
// then all v4 REDs. (Correctness validated on silicon in R11/R12.)
// ---------------------------------------------------------------------------
template<int LAYER>
__global__ __launch_bounds__(256) void scatter_kernel(
    const int* __restrict__ src, const int* __restrict__ dst, int E)
{
    constexpr int F = (LAYER == 1) ? HH1 : HH2;
    constexpr int NIT = F / 128;   // float4s per lane per edge
    constexpr int EPW = 4;         // edges per warp
    const float* hs = (LAYER == 1) ? g_hs1  : g_hs2;
    float* agg      = (LAYER == 1) ? g_agg1 : g_agg2;

    int g = blockIdx.x * blockDim.x + threadIdx.x;
    int warp = g >> 5;
    int lane = g & 31;
    int e0 = warp * EPW;
    if (e0 >= E) return;

    int s[EPW], d[EPW];
#pragma unroll
    for (int w = 0; w < EPW; w++) {
        int e = e0 + w;
        if (e < E) {
            s[w] = __ldg(src + e);    // warp-uniform broadcast load
            d[w] = __ldg(dst + e);
        }
    }

    float4 v[EPW][NIT];
#pragma unroll
    for (int w = 0; w < EPW; w++) {
        if (e0 + w < E) {
            const float4* sp = (const float4*)(hs + (size_t)s[w] * F);
#pragma unroll
            for (int i = 0; i < NIT; i++)
                v[w][i] = __ldg(sp + lane + i * 32);
        }
    }

#pragma unroll
    for (int w = 0; w < EPW; w++) {
        if (e0 + w < E) {
            float4* dp = (float4*)(agg + (size_t)d[w] * F);
#pragma unroll
            for (int i = 0; i < NIT; i++)
                asm volatile("red.global.add.v4.f32 [%0], {%1, %2, %3, %4};"
                             :: "l"(dp + lane + i * 32),
                                "f"(v[w][i].x), "f"(v[w][i].y),
                                "f"(v[w][i].z), "f"(v[w][i].w)
                             : "memory");
        }
    }
}

// ---------------------------------------------------------------------------
// Final: out = dinv[row]*agg2 + b2
// ---------------------------------------------------------------------------
__global__ void finalize_kernel(const float* __restrict__ b2,
                                float* __restrict__ out, int n)
{
    int idx = blockIdx.x * blockDim.x + threadIdx.x;   // over n * HH2/4
    int total = n * (HH2 / 4);
    if (idx >= total) return;
    int i  = idx / (HH2 / 4);
    int j4 = idx % (HH2 / 4);
    float dv = g_dinv[i];
    float4 v  = *(const float4*)(g_agg2 + (size_t)i * HH2 + j4 * 4);
    float4 bb = *(const float4*)(b2 + j4 * 4);
    float4 o;
    o.x = fmaf(dv, v.x, bb.x);
    o.y = fmaf(dv, v.y, bb.y);
    o.z = fmaf(dv, v.z, bb.z);
    o.w = fmaf(dv, v.w, bb.w);
    *(float4*)(out + (size_t)i * HH2 + j4 * 4) = o;
}

// ---------------------------------------------------------------------------
extern "C" void kernel_launch(void* const* d_in, const int* in_sizes, int n_in,
                              void* d_out, int out_size)
{
    const float* x  = (const float*)d_in[0];
    const float* W1 = (const float*)d_in[1];
    const float* b1 = (const float*)d_in[2];
    const float* W2 = (const float*)d_in[3];
    const float* b2 = (const float*)d_in[4];
    const int* edge = (const int*)d_in[5];

    int n = in_sizes[0] / DIN;
    int E = in_sizes[5] / 2;
    const int* src = edge;
    const int* dst = edge + E;
    float* out = (float*)d_out;

    int tb = 256;

    deg_init_kernel<<<(n + tb - 1) / tb, tb>>>(n);
    deg_edge_kernel<<<592, 512>>>(dst, E);   // ~4 blocks/SM grid-stride
    dinv_kernel<<<(n + tb - 1) / tb, tb>>>(n);

    dim3 g1(HH1 / 128, (n + 127) / 128);
    gemm_kernel<1><<<g1, 256>>>(x, W1, nullptr, n);

    // EPW=4 edges/warp: threads = ceil(E/4) warps * 32
    long long warps = ((long long)E + 3) / 4;
    long long t1 = warps * 32;
    scatter_kernel<1><<<(unsigned)((t1 + tb - 1) / tb), tb>>>(src, dst, E);

    dim3 g2(HH2 / 128, (n + 127) / 128);
    gemm_kernel<2><<<g2, 256>>>(nullptr, W2, b1, n);

    scatter_kernel<2><<<(unsigned)((t1 + tb - 1) / tb), tb>>>(src, dst, E);

    finalize_kernel<<<(n * (HH2 / 4) + tb - 1) / tb, tb>>>(b2, out, n);
}